// round 2
// baseline (speedup 1.0000x reference)
#include <cuda_runtime.h>
#include <math.h>

// Problem dims
#define BB 8
#define SS 16
#define HH 32
#define WW 32
#define EE 128
#define NHH 8
#define HDD 16
#define NTOK (BB*SS*HH*WW)      // 131072
#define NPIX (BB*HH*WW)          // 8192 pixels per step (b,y,x)

// ---------------- scratch (device globals; no allocation allowed) ----------
__device__ float g_x1 [NTOK*EE];        // post silu / post LN
__device__ float g_qkv[NTOK*3*EE];      // qkv
__device__ float g_ao [NTOK*EE];        // attention output
__device__ float g_xr [NTOK*EE];        // residual out (conv x-input), token-major [tok][e]
__device__ float g_h  [NPIX*EE];        // hidden state, [b*1024+pix][e]
__device__ float g_c  [NPIX*EE];        // cell state
__device__ float g_cc [NPIX*4*EE];      // conv output, [b*1024+pix][512]

// ---------------- GEMM: C[M x N] = A[M x 128] @ B[128 x N] ------------------
// MODE 0: A=inputs param, silu, -> g_x1
// MODE 1: A=g_x1,          none, -> g_qkv (N=384)
// MODE 2: A=g_ao,  +inputs residual, -> g_xr
template<int N_, int MODE>
__global__ void gemm_kernel(const float* __restrict__ Ap,
                            const float* __restrict__ Bm,
                            const float* __restrict__ Rp)
{
    const float* A = (MODE == 0) ? Ap : (MODE == 1 ? g_x1 : g_ao);
    float*       C = (MODE == 0) ? g_x1 : (MODE == 1 ? g_qkv : g_xr);

    __shared__ float As[8][64];
    __shared__ float Bs[8][64];

    const int m0 = blockIdx.x * 64;
    const int n0 = blockIdx.y * 64;
    const int t  = threadIdx.x;
    const int tx = t & 15;      // N dir
    const int ty = t >> 4;      // M dir

    float acc[4][4] = {};

    for (int k0 = 0; k0 < 128; k0 += 8) {
        #pragma unroll
        for (int it = 0; it < 2; it++) {
            int idx = t + it * 256;
            int kk = idx & 7, mm = idx >> 3;
            As[kk][mm] = A[(m0 + mm) * 128 + k0 + kk];
        }
        #pragma unroll
        for (int it = 0; it < 2; it++) {
            int idx = t + it * 256;
            int nn = idx & 63, kk = idx >> 6;
            Bs[kk][nn] = Bm[(k0 + kk) * N_ + n0 + nn];
        }
        __syncthreads();
        #pragma unroll
        for (int kk = 0; kk < 8; kk++) {
            float4 a4 = *(const float4*)&As[kk][ty * 4];
            float4 b4 = *(const float4*)&Bs[kk][tx * 4];
            float a[4] = {a4.x, a4.y, a4.z, a4.w};
            float b[4] = {b4.x, b4.y, b4.z, b4.w};
            #pragma unroll
            for (int i = 0; i < 4; i++)
                #pragma unroll
                for (int j = 0; j < 4; j++)
                    acc[i][j] += a[i] * b[j];
        }
        __syncthreads();
    }

    #pragma unroll
    for (int i = 0; i < 4; i++) {
        int m = m0 + ty * 4 + i;
        #pragma unroll
        for (int j = 0; j < 4; j++) {
            int n = n0 + tx * 4 + j;
            float v = acc[i][j];
            if (MODE == 0) v = v / (1.0f + expf(-v));       // silu
            if (MODE == 2) v += Rp[m * N_ + n];             // residual
            C[m * N_ + n] = v;
        }
    }
}

// ---------------- LayerNorm (in place on g_x1), one warp per token ---------
__global__ void ln_kernel(const float* __restrict__ gamma,
                          const float* __restrict__ beta)
{
    int tok  = blockIdx.x * 8 + (threadIdx.x >> 5);
    int lane = threadIdx.x & 31;
    float4 v = *(float4*)&g_x1[tok * 128 + lane * 4];
    float s = v.x + v.y + v.z + v.w;
    float q = v.x * v.x + v.y * v.y + v.z * v.z + v.w * v.w;
    #pragma unroll
    for (int off = 16; off > 0; off >>= 1) {
        s += __shfl_xor_sync(0xFFFFFFFF, s, off);
        q += __shfl_xor_sync(0xFFFFFFFF, q, off);
    }
    float mu  = s * (1.0f / 128.0f);
    float var = q * (1.0f / 128.0f) - mu * mu;
    float rs  = rsqrtf(var + 1e-5f);
    float4 g = *(const float4*)&gamma[lane * 4];
    float4 b = *(const float4*)&beta [lane * 4];
    v.x = (v.x - mu) * rs * g.x + b.x;
    v.y = (v.y - mu) * rs * g.y + b.y;
    v.z = (v.z - mu) * rs * g.z + b.z;
    v.w = (v.w - mu) * rs * g.w + b.w;
    *(float4*)&g_x1[tok * 128 + lane * 4] = v;
}

// ---------------- Attention: 16 groups/block, thread = query row -----------
__global__ void attn_kernel()
{
    __shared__ float ks[16][16][16];
    __shared__ float vs[16][16][16];

    const int t  = threadIdx.x;
    const int gl = t >> 4;          // group within block
    const int sq = t & 15;          // query position
    const int g  = blockIdx.x * 16 + gl;
    const int nh = g & 7;
    const int w  = (g >> 3) & 31;
    const int h  = (g >> 8) & 31;
    const int b  = g >> 13;

    const int tok = (b * 16 + sq) * 1024 + h * 32 + w;
    const float* p = g_qkv + tok * 384 + nh * 48;

    float q[16];
    {
        float4 q0 = *(const float4*)(p + 0);
        float4 q1 = *(const float4*)(p + 4);
        float4 q2 = *(const float4*)(p + 8);
        float4 q3 = *(const float4*)(p + 12);
        q[0]=q0.x; q[1]=q0.y; q[2]=q0.z; q[3]=q0.w;
        q[4]=q1.x; q[5]=q1.y; q[6]=q1.z; q[7]=q1.w;
        q[8]=q2.x; q[9]=q2.y; q[10]=q2.z; q[11]=q2.w;
        q[12]=q3.x; q[13]=q3.y; q[14]=q3.z; q[15]=q3.w;
    }
    #pragma unroll
    for (int c = 0; c < 4; c++) {
        *(float4*)&ks[gl][sq][c * 4] = *(const float4*)(p + 16 + c * 4);
        *(float4*)&vs[gl][sq][c * 4] = *(const float4*)(p + 32 + c * 4);
    }
    __syncthreads();

    float sc[16];
    float mx = -1e30f;
    #pragma unroll
    for (int l = 0; l < 16; l++) {
        float d = 0.0f;
        #pragma unroll
        for (int dd = 0; dd < 16; dd++) d += q[dd] * ks[gl][l][dd];
        float m = (l <= sq) ? 1.0f : -1000.0f;     // faithful to source mask
        sc[l] = d * 0.25f + m;
        mx = fmaxf(mx, sc[l]);
    }
    float sum = 0.0f;
    #pragma unroll
    for (int l = 0; l < 16; l++) { sc[l] = expf(sc[l] - mx); sum += sc[l]; }
    float inv = 1.0f / sum;

    float o[16] = {};
    #pragma unroll
    for (int l = 0; l < 16; l++) {
        float pl = sc[l] * inv;
        #pragma unroll
        for (int dd = 0; dd < 16; dd++) o[dd] += pl * vs[gl][l][dd];
    }
    float* dst = g_ao + tok * 128 + nh * 16;
    #pragma unroll
    for (int c = 0; c < 4; c++) {
        float4 v4 = {o[c*4+0], o[c*4+1], o[c*4+2], o[c*4+3]};
        *(float4*)(dst + c * 4) = v4;
    }
}

// ---------------- zero h/c ----------------
__global__ void zero_hc_kernel()
{
    int idx = blockIdx.x * 256 + threadIdx.x;
    g_h[idx] = 0.0f;
    g_c[idx] = 0.0f;
}

// ---------------- ConvLSTM conv step: 3x3 SAME, 256 ic -> 512 oc -----------
// grid (8 ocTiles, 8 yTiles, 8 b), 256 threads.
// Block: 4 rows x 32 x-cols x 64 oc. Thread: x = t&31, ocg = t>>5 (8 oc, 4 rows).
__global__ void conv_kernel(int s, const float* __restrict__ convk)
{
    __shared__ float in_s[8 * 6 * 34];     // [i][r][xx]: i*204 + r*34 + xx
    __shared__ float w_s [64 * 8 * 9];     // [o][i][k]:  o*72  + i*9  + k

    const int b   = blockIdx.z;
    const int y0  = blockIdx.y * 4;
    const int ocT = blockIdx.x * 64;
    const int t   = threadIdx.x;
    const int x   = t & 31;
    const int ocg = t >> 5;

    float acc[4][8] = {};

    const float* xpart = g_xr + (b * 16 + s) * 1024 * 128;  // [pix][128]
    const float* hpart = g_h  + b * 1024 * 128;             // [pix][128]

    for (int ic0 = 0; ic0 < 256; ic0 += 8) {
        // input tile: 8 ic x 6 rows (y0-1..y0+4) x 34 cols (-1..32)
        for (int idx = t; idx < 8 * 6 * 34; idx += 256) {
            int i   = idx & 7;
            int rest = idx >> 3;
            int xx  = rest % 34;
            int r   = rest / 34;
            int gy  = y0 - 1 + r;
            int gx  = xx - 1;
            float v = 0.0f;
            if ((unsigned)gy < 32u && (unsigned)gx < 32u) {
                int ic  = ic0 + i;
                int pix = gy * 32 + gx;
                v = (ic < 128) ? xpart[pix * 128 + ic]
                               : hpart[pix * 128 + (ic - 128)];
            }
            in_s[i * 204 + r * 34 + xx] = v;
        }
        // weights: 64 oc x 8 ic x 9
        for (int idx = t; idx < 64 * 8 * 9; idx += 256) {
            int k    = idx % 9;
            int rest = idx / 9;
            int i    = rest & 7;
            int o    = rest >> 3;
            w_s[idx] = convk[((ocT + o) * 256 + ic0 + i) * 9 + k];
        }
        __syncthreads();

        #pragma unroll 1
        for (int i = 0; i < 8; i++) {
            const float* ip = &in_s[i * 204 + x];
            const float* wb = &w_s[ocg * 8 * 72 + i * 9];
            #pragma unroll
            for (int ky = 0; ky < 3; ky++) {
                #pragma unroll
                for (int kx = 0; kx < 3; kx++) {
                    float a0 = ip[(0 + ky) * 34 + kx];
                    float a1 = ip[(1 + ky) * 34 + kx];
                    float a2 = ip[(2 + ky) * 34 + kx];
                    float a3 = ip[(3 + ky) * 34 + kx];
                    const float* wp = wb + ky * 3 + kx;
                    #pragma unroll
                    for (int oo = 0; oo < 8; oo++) {
                        float wv = wp[oo * 72];
                        acc[0][oo] += a0 * wv;
                        acc[1][oo] += a1 * wv;
                        acc[2][oo] += a2 * wv;
                        acc[3][oo] += a3 * wv;
                    }
                }
            }
        }
        __syncthreads();
    }

    #pragma unroll
    for (int r = 0; r < 4; r++) {
        int pix = (y0 + r) * 32 + x;
        float* dst = g_cc + (b * 1024 + pix) * 512 + ocT + ocg * 8;
        float4 v0 = {acc[r][0], acc[r][1], acc[r][2], acc[r][3]};
        float4 v1 = {acc[r][4], acc[r][5], acc[r][6], acc[r][7]};
        *(float4*)(dst + 0) = v0;
        *(float4*)(dst + 4) = v1;
    }
}

// ---------------- LSTM gates + state update + output write -----------------
__global__ void gates_kernel(int s, float* __restrict__ out)
{
    int idx = blockIdx.x * 256 + threadIdx.x;   // over NPIX*EE = 1,048,576
    int e      = idx & 127;
    int pix_b  = idx >> 7;                      // b*1024 + pix
    const float* cc = g_cc + pix_b * 512;
    float ci = cc[e];
    float cf = cc[128 + e];
    float co = cc[256 + e];
    float cg = cc[384 + e];
    float c  = g_c[idx];
    float si = 1.0f / (1.0f + expf(-ci));
    float sf = 1.0f / (1.0f + expf(-cf));
    float so = 1.0f / (1.0f + expf(-co));
    float cn = sf * c + si * tanhf(cg);
    float hn = so * tanhf(cn);
    g_c[idx] = cn;
    g_h[idx] = hn;
    int b   = pix_b >> 10;
    int pix = pix_b & 1023;
    out[((b * 16 + s) * 1024 + pix) * 128 + e] = hn;
}

// ---------------- launch ----------------------------------------------------
extern "C" void kernel_launch(void* const* d_in, const int* in_sizes, int n_in,
                              void* d_out, int out_size)
{
    const float* inputs = (const float*)d_in[0];
    const float* W_proj = (const float*)d_in[1];
    const float* gamma  = (const float*)d_in[2];
    const float* beta   = (const float*)d_in[3];
    const float* W_in   = (const float*)d_in[4];
    const float* W_out  = (const float*)d_in[5];
    const float* convk  = (const float*)d_in[6];
    float* out = (float*)d_out;

    // 1) x = silu(inputs @ W_proj)
    gemm_kernel<128, 0><<<dim3(NTOK / 64, 2), 256>>>(inputs, W_proj, nullptr);
    // 2) LayerNorm (in place)
    ln_kernel<<<NTOK / 8, 256>>>(gamma, beta);
    // 3) qkv = x @ W_in
    gemm_kernel<384, 1><<<dim3(NTOK / 64, 6), 256>>>(nullptr, W_in, nullptr);
    // 4) attention
    attn_kernel<<<(BB * HH * WW * NHH) / 16, 256>>>();
    // 5) x = ao @ W_out + inputs
    gemm_kernel<128, 2><<<dim3(NTOK / 64, 2), 256>>>(nullptr, W_out, inputs);
    // 6) h = c = 0
    zero_hc_kernel<<<(NPIX * EE) / 256, 256>>>();
    // 7) ConvLSTM scan over S
    for (int s = 0; s < SS; s++) {
        conv_kernel<<<dim3(8, 8, 8), 256>>>(s, convk);
        gates_kernel<<<(NPIX * EE) / 256, 256>>>(s, out);
    }
}

// round 5
// speedup vs baseline: 2.7913x; 2.7913x over previous
#include <cuda_runtime.h>
#include <math.h>
#include <stdint.h>

// Problem dims
#define BB 8
#define SS 16
#define HH 32
#define WW 32
#define EE 128
#define NHH 8
#define HDD 16
#define NTOK (BB*SS*HH*WW)      // 131072
#define NPIX (BB*HH*WW)          // 8192 pixels per step (b,y,x)

// ---------------- scratch (device globals; no allocation allowed) ----------
__device__ float g_x1 [NTOK*EE];        // post silu / post LN
__device__ float g_qkv[NTOK*3*EE];      // qkv
__device__ float g_ao [NTOK*EE];        // attention output
__device__ float g_xr [NTOK*EE];        // residual out (conv x-input), token-major [tok][e]
__device__ float g_h  [NPIX*EE];        // hidden state, [b*1024+pix][e]
__device__ float g_c  [NPIX*EE];        // cell state
__device__ float g_cc [NPIX*4*EE];      // conv output, [b*1024+pix][512]
__device__ float g_pad[BB*256*34*34];   // padded planar conv input (tf32-rounded)
__device__ float g_wp [9*256*512];      // packed conv weights [tap][ic][oc] (tf32-rounded)

// tf32 round-to-nearest helper
__device__ __forceinline__ float tf32r(float x) {
    uint32_t u;
    asm("cvt.rna.tf32.f32 %0, %1;" : "=r"(u) : "f"(x));
    return __uint_as_float(u);
}

// ---------------- GEMM: C[M x N] = A[M x 128] @ B[128 x N] ------------------
template<int N_, int MODE>
__global__ void gemm_kernel(const float* __restrict__ Ap,
                            const float* __restrict__ Bm,
                            const float* __restrict__ Rp)
{
    const float* A = (MODE == 0) ? Ap : (MODE == 1 ? g_x1 : g_ao);
    float*       C = (MODE == 0) ? g_x1 : (MODE == 1 ? g_qkv : g_xr);

    __shared__ float As[8][64];
    __shared__ float Bs[8][64];

    const int m0 = blockIdx.x * 64;
    const int n0 = blockIdx.y * 64;
    const int t  = threadIdx.x;
    const int tx = t & 15;      // N dir
    const int ty = t >> 4;      // M dir

    float acc[4][4] = {};

    for (int k0 = 0; k0 < 128; k0 += 8) {
        #pragma unroll
        for (int it = 0; it < 2; it++) {
            int idx = t + it * 256;
            int kk = idx & 7, mm = idx >> 3;
            As[kk][mm] = A[(m0 + mm) * 128 + k0 + kk];
        }
        #pragma unroll
        for (int it = 0; it < 2; it++) {
            int idx = t + it * 256;
            int nn = idx & 63, kk = idx >> 6;
            Bs[kk][nn] = Bm[(k0 + kk) * N_ + n0 + nn];
        }
        __syncthreads();
        #pragma unroll
        for (int kk = 0; kk < 8; kk++) {
            float4 a4 = *(const float4*)&As[kk][ty * 4];
            float4 b4 = *(const float4*)&Bs[kk][tx * 4];
            float a[4] = {a4.x, a4.y, a4.z, a4.w};
            float b[4] = {b4.x, b4.y, b4.z, b4.w};
            #pragma unroll
            for (int i = 0; i < 4; i++)
                #pragma unroll
                for (int j = 0; j < 4; j++)
                    acc[i][j] += a[i] * b[j];
        }
        __syncthreads();
    }

    #pragma unroll
    for (int i = 0; i < 4; i++) {
        int m = m0 + ty * 4 + i;
        #pragma unroll
        for (int j = 0; j < 4; j++) {
            int n = n0 + tx * 4 + j;
            float v = acc[i][j];
            if (MODE == 0) v = v / (1.0f + expf(-v));       // silu
            if (MODE == 2) v += Rp[m * N_ + n];             // residual
            C[m * N_ + n] = v;
        }
    }
}

// ---------------- LayerNorm (in place on g_x1), one warp per token ---------
__global__ void ln_kernel(const float* __restrict__ gamma,
                          const float* __restrict__ beta)
{
    int tok  = blockIdx.x * 8 + (threadIdx.x >> 5);
    int lane = threadIdx.x & 31;
    float4 v = *(float4*)&g_x1[tok * 128 + lane * 4];
    float s = v.x + v.y + v.z + v.w;
    float q = v.x * v.x + v.y * v.y + v.z * v.z + v.w * v.w;
    #pragma unroll
    for (int off = 16; off > 0; off >>= 1) {
        s += __shfl_xor_sync(0xFFFFFFFF, s, off);
        q += __shfl_xor_sync(0xFFFFFFFF, q, off);
    }
    float mu  = s * (1.0f / 128.0f);
    float var = q * (1.0f / 128.0f) - mu * mu;
    float rs  = rsqrtf(var + 1e-5f);
    float4 g = *(const float4*)&gamma[lane * 4];
    float4 b = *(const float4*)&beta [lane * 4];
    v.x = (v.x - mu) * rs * g.x + b.x;
    v.y = (v.y - mu) * rs * g.y + b.y;
    v.z = (v.z - mu) * rs * g.z + b.z;
    v.w = (v.w - mu) * rs * g.w + b.w;
    *(float4*)&g_x1[tok * 128 + lane * 4] = v;
}

// ---------------- Attention: 16 groups/block, thread = query row -----------
__global__ void attn_kernel()
{
    __shared__ float ks[16][16][16];
    __shared__ float vs[16][16][16];

    const int t  = threadIdx.x;
    const int gl = t >> 4;          // group within block
    const int sq = t & 15;          // query position
    const int g  = blockIdx.x * 16 + gl;
    const int nh = g & 7;
    const int w  = (g >> 3) & 31;
    const int h  = (g >> 8) & 31;
    const int b  = g >> 13;

    const int tok = (b * 16 + sq) * 1024 + h * 32 + w;
    const float* p = g_qkv + tok * 384 + nh * 48;

    float q[16];
    {
        float4 q0 = *(const float4*)(p + 0);
        float4 q1 = *(const float4*)(p + 4);
        float4 q2 = *(const float4*)(p + 8);
        float4 q3 = *(const float4*)(p + 12);
        q[0]=q0.x; q[1]=q0.y; q[2]=q0.z; q[3]=q0.w;
        q[4]=q1.x; q[5]=q1.y; q[6]=q1.z; q[7]=q1.w;
        q[8]=q2.x; q[9]=q2.y; q[10]=q2.z; q[11]=q2.w;
        q[12]=q3.x; q[13]=q3.y; q[14]=q3.z; q[15]=q3.w;
    }
    #pragma unroll
    for (int c = 0; c < 4; c++) {
        *(float4*)&ks[gl][sq][c * 4] = *(const float4*)(p + 16 + c * 4);
        *(float4*)&vs[gl][sq][c * 4] = *(const float4*)(p + 32 + c * 4);
    }
    __syncthreads();

    float sc[16];
    float mx = -1e30f;
    #pragma unroll
    for (int l = 0; l < 16; l++) {
        float d = 0.0f;
        #pragma unroll
        for (int dd = 0; dd < 16; dd++) d += q[dd] * ks[gl][l][dd];
        float m = (l <= sq) ? 1.0f : -1000.0f;     // faithful to source mask
        sc[l] = d * 0.25f + m;
        mx = fmaxf(mx, sc[l]);
    }
    float sum = 0.0f;
    #pragma unroll
    for (int l = 0; l < 16; l++) { sc[l] = expf(sc[l] - mx); sum += sc[l]; }
    float inv = 1.0f / sum;

    float o[16] = {};
    #pragma unroll
    for (int l = 0; l < 16; l++) {
        float pl = sc[l] * inv;
        #pragma unroll
        for (int dd = 0; dd < 16; dd++) o[dd] += pl * vs[gl][l][dd];
    }
    float* dst = g_ao + tok * 128 + nh * 16;
    #pragma unroll
    for (int c = 0; c < 4; c++) {
        float4 v4 = {o[c*4+0], o[c*4+1], o[c*4+2], o[c*4+3]};
        *(float4*)(dst + c * 4) = v4;
    }
}

// ---------------- zero h/c ----------------
__global__ void zero_hc_kernel()
{
    int idx = blockIdx.x * 256 + threadIdx.x;
    g_h[idx] = 0.0f;
    g_c[idx] = 0.0f;
}

// ---------------- zero padded input buffer (borders stay 0 forever) --------
__global__ void zero_pad_kernel()
{
    int idx = blockIdx.x * 256 + threadIdx.x;
    if (idx < BB * 256 * 34 * 34) g_pad[idx] = 0.0f;
}

// ---------------- weight prepack: conv_k[oc][ic][ky][kx] -> g_wp[tap][ic][oc]
__global__ void wprep_kernel(const float* __restrict__ convk)
{
    int idx = blockIdx.x * 256 + threadIdx.x;   // 9*256*512 = 1,179,648
    if (idx >= 9 * 256 * 512) return;
    int oc = idx & 511;
    int ic = (idx >> 9) & 255;
    int tp = idx >> 17;
    g_wp[idx] = tf32r(convk[(oc * 256 + ic) * 9 + tp]);
}

// ---------------- pack per-step conv input into planar padded buffer -------
// grid (32 rows, 8 ic-groups, 8 b), 256 threads. smem transpose 32px x 32ch.
__global__ void pack_kernel(int s)
{
    __shared__ float tile[32][33];
    const int b   = blockIdx.z;
    const int icg = blockIdx.y;
    const int y   = blockIdx.x;
    const int t   = threadIdx.x;
    const int e   = icg * 32 + (t & 31);

    #pragma unroll
    for (int it = 0; it < 4; it++) {
        int x   = (t >> 5) + it * 8;
        int pix = y * 32 + x;
        float v = (e < 128)
            ? g_xr[((b * 16 + s) * 1024 + pix) * 128 + e]
            : g_h [(b * 1024 + pix) * 128 + (e - 128)];
        tile[x][t & 31] = v;
    }
    __syncthreads();
    #pragma unroll
    for (int it = 0; it < 4; it++) {
        int icl = (t >> 5) + it * 8;
        int ic  = icg * 32 + icl;
        int x   = t & 31;
        g_pad[((b * 256 + ic) * 34 + (y + 1)) * 34 + (x + 1)] = tf32r(tile[x][icl]);
    }
}

// ---------------- tensor-core conv: tf32 mma.sync m16n8k8 ------------------
// Block: M=128 px (4 rows x 32 cols) x N=64 oc. 8 warps: wm = warp&3 (row),
// wn = warp>>2 (oc half). K loop: 32 ic-chunks of 8; per chunk, 9 taps x 1 k8.
__global__ void __launch_bounds__(256) conv_mma_kernel(int s)
{
    __shared__ uint32_t in_s[8 * 6 * 34];    // [ic][row 6][col 34], stride 204
    __shared__ uint32_t w_s [9 * 8 * 72];    // [tap][ic][oc(64, pad 72)]

    const int b   = blockIdx.z;
    const int y0  = blockIdx.y * 4;
    const int ocB = blockIdx.x * 64;
    const int t   = threadIdx.x;
    const int lane = t & 31;
    const int warp = t >> 5;
    const int wm  = warp & 3;       // conv row within 4-row strip
    const int wn  = warp >> 2;      // 0/1: oc 32-half
    const int icl = lane & 3;       // k index base within k8
    const int ocl = wn * 32 + (lane >> 2);

    float acc[2][4][4] = {};

    for (int ic0 = 0; ic0 < 256; ic0 += 8) {
        // input halo tile: 8 ic x 6 padded rows (y0..y0+5) x 34 cols
        for (int idx = t; idx < 8 * 6 * 34; idx += 256) {
            int i  = idx / 204;
            int r  = (idx % 204) / 34;
            int xx = idx % 34;
            in_s[idx] = __float_as_uint(
                g_pad[((b * 256 + ic0 + i) * 34 + (y0 + r)) * 34 + xx]);
        }
        // weights: 9 taps x 8 ic x 64 oc
        for (int idx = t; idx < 9 * 8 * 64; idx += 256) {
            int o  = idx & 63;
            int i  = (idx >> 6) & 7;
            int tp = idx >> 9;
            w_s[(tp * 8 + i) * 72 + o] =
                __float_as_uint(g_wp[(tp * 256 + ic0 + i) * 512 + ocB + o]);
        }
        __syncthreads();

        #pragma unroll
        for (int tp = 0; tp < 9; tp++) {
            const int ky = tp / 3, kx = tp % 3;
            uint32_t bf[4][2];
            #pragma unroll
            for (int g = 0; g < 4; g++) {
                bf[g][0] = w_s[(tp * 8 + icl    ) * 72 + ocl + g * 8];
                bf[g][1] = w_s[(tp * 8 + icl + 4) * 72 + ocl + g * 8];
            }
            const int rr = wm + ky;
            #pragma unroll
            for (int f = 0; f < 2; f++) {
                int xx = f * 16 + (lane >> 2) + kx;
                uint32_t a0 = in_s[(icl * 6 + rr) * 34 + xx];
                uint32_t a1 = in_s[(icl * 6 + rr) * 34 + xx + 8];
                uint32_t a2 = in_s[((icl + 4) * 6 + rr) * 34 + xx];
                uint32_t a3 = in_s[((icl + 4) * 6 + rr) * 34 + xx + 8];
                #pragma unroll
                for (int g = 0; g < 4; g++) {
                    asm volatile(
                        "mma.sync.aligned.m16n8k8.row.col.f32.tf32.tf32.f32 "
                        "{%0,%1,%2,%3}, {%4,%5,%6,%7}, {%8,%9}, {%0,%1,%2,%3};"
                        : "+f"(acc[f][g][0]), "+f"(acc[f][g][1]),
                          "+f"(acc[f][g][2]), "+f"(acc[f][g][3])
                        : "r"(a0), "r"(a1), "r"(a2), "r"(a3),
                          "r"(bf[g][0]), "r"(bf[g][1]));
                }
            }
        }
        __syncthreads();
    }

    // write C: rows = f*16 + lane>>2 (+8), cols = 2*(lane&3) (+1)
    #pragma unroll
    for (int f = 0; f < 2; f++) {
        #pragma unroll
        for (int g = 0; g < 4; g++) {
            int n  = ocB + wn * 32 + g * 8 + 2 * (lane & 3);
            int x0 = f * 16 + (lane >> 2);
            int pix0 = (y0 + wm) * 32 + x0;
            int pix1 = pix0 + 8;
            float2 v0 = {acc[f][g][0], acc[f][g][1]};
            float2 v1 = {acc[f][g][2], acc[f][g][3]};
            *(float2*)&g_cc[(b * 1024 + pix0) * 512 + n] = v0;
            *(float2*)&g_cc[(b * 1024 + pix1) * 512 + n] = v1;
        }
    }
}

// ---------------- LSTM gates + state update + output write -----------------
__global__ void gates_kernel(int s, float* __restrict__ out)
{
    int idx = blockIdx.x * 256 + threadIdx.x;   // over NPIX*EE = 1,048,576
    int e      = idx & 127;
    int pix_b  = idx >> 7;                      // b*1024 + pix
    const float* cc = g_cc + pix_b * 512;
    float ci = cc[e];
    float cf = cc[128 + e];
    float co = cc[256 + e];
    float cg = cc[384 + e];
    float c  = g_c[idx];
    float si = 1.0f / (1.0f + expf(-ci));
    float sf = 1.0f / (1.0f + expf(-cf));
    float so = 1.0f / (1.0f + expf(-co));
    float cn = sf * c + si * tanhf(cg);
    float hn = so * tanhf(cn);
    g_c[idx] = cn;
    g_h[idx] = hn;
    int b   = pix_b >> 10;
    int pix = pix_b & 1023;
    out[((b * 16 + s) * 1024 + pix) * 128 + e] = hn;
}

// ---------------- launch ----------------------------------------------------
extern "C" void kernel_launch(void* const* d_in, const int* in_sizes, int n_in,
                              void* d_out, int out_size)
{
    const float* inputs = (const float*)d_in[0];
    const float* W_proj = (const float*)d_in[1];
    const float* gamma  = (const float*)d_in[2];
    const float* beta   = (const float*)d_in[3];
    const float* W_in   = (const float*)d_in[4];
    const float* W_out  = (const float*)d_in[5];
    const float* convk  = (const float*)d_in[6];
    float* out = (float*)d_out;

    // 1) x = silu(inputs @ W_proj)
    gemm_kernel<128, 0><<<dim3(NTOK / 64, 2), 256>>>(inputs, W_proj, nullptr);
    // 2) LayerNorm (in place)
    ln_kernel<<<NTOK / 8, 256>>>(gamma, beta);
    // 3) qkv = x @ W_in
    gemm_kernel<384, 1><<<dim3(NTOK / 64, 6), 256>>>(nullptr, W_in, nullptr);
    // 4) attention
    attn_kernel<<<(BB * HH * WW * NHH) / 16, 256>>>();
    // 5) x = ao @ W_out + inputs
    gemm_kernel<128, 2><<<dim3(NTOK / 64, 2), 256>>>(nullptr, W_out, inputs);
    // 6) init state + pad borders + weights
    zero_hc_kernel<<<(NPIX * EE) / 256, 256>>>();
    zero_pad_kernel<<<(BB * 256 * 34 * 34 + 255) / 256, 256>>>();
    wprep_kernel<<<(9 * 256 * 512 + 255) / 256, 256>>>(convk);
    // 7) ConvLSTM scan over S
    for (int s = 0; s < SS; s++) {
        pack_kernel<<<dim3(32, 8, 8), 256>>>(s);
        conv_mma_kernel<<<dim3(8, 8, 8), 256>>>(s);
        gates_kernel<<<(NPIX * EE) / 256, 256>>>(s, out);
    }
}

// round 6
// speedup vs baseline: 5.0833x; 1.8211x over previous
#include <cuda_runtime.h>
#include <math.h>
#include <stdint.h>

// Problem dims
#define BB 8
#define SS 16
#define HH 32
#define WW 32
#define EE 128
#define NHH 8
#define HDD 16
#define NTOK (BB*SS*HH*WW)      // 131072
#define NPIX (BB*HH*WW)          // 8192

// ---------------- scratch (device globals) ----------------------------------
__device__ float g_x1 [NTOK*EE];
__device__ float g_qkv[NTOK*3*EE];
__device__ float g_ao [NTOK*EE];
__device__ float g_xr [NTOK*EE];
__device__ float g_h  [NPIX*EE];
__device__ float g_c  [NPIX*EE];
__device__ float g_cc [NPIX*4*EE];
__device__ float g_pad[BB*256*34*36];   // padded planar conv input, row stride 36
__device__ float g_wp [9*256*512];      // packed conv weights [tap][ic][oc]

__device__ __forceinline__ float tf32r(float x) {
    uint32_t u;
    asm("cvt.rna.tf32.f32 %0, %1;" : "=r"(u) : "f"(x));
    return __uint_as_float(u);
}
__device__ __forceinline__ uint32_t sm_u32(const void* p) {
    return (uint32_t)__cvta_generic_to_shared(p);
}
__device__ __forceinline__ void cpa16(uint32_t dst, const float* src) {
    asm volatile("cp.async.cg.shared.global [%0], [%1], 16;\n" :: "r"(dst), "l"(src));
}

// ---------------- tf32 MMA GEMM: C[M x N_] = A[M x 128] @ B[128 x N_] -------
// Block: 128 rows x 128 cols, 8 warps (wm 0..3 = 32-row quarter, wn 0..1 = 64-col half).
// Whole K=128 staged in smem once. MODE 0: silu -> g_x1; 1: -> g_qkv; 2: +res -> g_xr.
template<int N_, int MODE>
__global__ void __launch_bounds__(256) gemm_mma_kernel(const float* __restrict__ Ap,
                                                       const float* __restrict__ Bm,
                                                       const float* __restrict__ Rp)
{
    extern __shared__ float gsm[];
    float* As = gsm;            // 128 x (stride 132)
    float* Bs = gsm + 16896;    // 128 x (stride 136)

    const float* A = (MODE == 0) ? Ap : (MODE == 1 ? g_x1 : g_ao);
    float*       C = (MODE == 0) ? g_x1 : (MODE == 1 ? g_qkv : g_xr);

    const int m0 = blockIdx.x * 128;
    const int n0 = blockIdx.y * 128;
    const int t = threadIdx.x, lane = t & 31, warp = t >> 5;
    const int wm = warp & 3, wn = warp >> 2;

    #pragma unroll
    for (int j = 0; j < 16; j++) {
        int idx = t + j * 256;
        int row = idx >> 5, col4 = idx & 31;
        float4 v = *(const float4*)&A[(m0 + row) * 128 + col4 * 4];
        v.x = tf32r(v.x); v.y = tf32r(v.y); v.z = tf32r(v.z); v.w = tf32r(v.w);
        *(float4*)&As[row * 132 + col4 * 4] = v;
    }
    #pragma unroll
    for (int j = 0; j < 16; j++) {
        int idx = t + j * 256;
        int k = idx >> 5, col4 = idx & 31;
        float4 v = *(const float4*)&Bm[k * N_ + n0 + col4 * 4];
        v.x = tf32r(v.x); v.y = tf32r(v.y); v.z = tf32r(v.z); v.w = tf32r(v.w);
        *(float4*)&Bs[k * 136 + col4 * 4] = v;
    }
    __syncthreads();

    float acc[2][8][4] = {};
    #pragma unroll
    for (int k8 = 0; k8 < 16; k8++) {
        uint32_t af[2][4], bfr[8][2];
        #pragma unroll
        for (int mi = 0; mi < 2; mi++) {
            const float* p = &As[(wm * 32 + mi * 16 + (lane >> 2)) * 132 + k8 * 8 + (lane & 3)];
            af[mi][0] = __float_as_uint(p[0]);
            af[mi][1] = __float_as_uint(p[8 * 132]);
            af[mi][2] = __float_as_uint(p[4]);
            af[mi][3] = __float_as_uint(p[8 * 132 + 4]);
        }
        #pragma unroll
        for (int ni = 0; ni < 8; ni++) {
            const float* p = &Bs[(k8 * 8 + (lane & 3)) * 136 + wn * 64 + ni * 8 + (lane >> 2)];
            bfr[ni][0] = __float_as_uint(p[0]);
            bfr[ni][1] = __float_as_uint(p[4 * 136]);
        }
        #pragma unroll
        for (int mi = 0; mi < 2; mi++)
            #pragma unroll
            for (int ni = 0; ni < 8; ni++) {
                asm volatile(
                    "mma.sync.aligned.m16n8k8.row.col.f32.tf32.tf32.f32 "
                    "{%0,%1,%2,%3}, {%4,%5,%6,%7}, {%8,%9}, {%0,%1,%2,%3};"
                    : "+f"(acc[mi][ni][0]), "+f"(acc[mi][ni][1]),
                      "+f"(acc[mi][ni][2]), "+f"(acc[mi][ni][3])
                    : "r"(af[mi][0]), "r"(af[mi][1]), "r"(af[mi][2]), "r"(af[mi][3]),
                      "r"(bfr[ni][0]), "r"(bfr[ni][1]));
            }
    }

    #pragma unroll
    for (int mi = 0; mi < 2; mi++)
        #pragma unroll
        for (int ni = 0; ni < 8; ni++) {
            int r0 = m0 + wm * 32 + mi * 16 + (lane >> 2);
            int cc = n0 + wn * 64 + ni * 8 + 2 * (lane & 3);
            float2 v0 = {acc[mi][ni][0], acc[mi][ni][1]};
            float2 v1 = {acc[mi][ni][2], acc[mi][ni][3]};
            if (MODE == 0) {
                v0.x = v0.x / (1.0f + expf(-v0.x)); v0.y = v0.y / (1.0f + expf(-v0.y));
                v1.x = v1.x / (1.0f + expf(-v1.x)); v1.y = v1.y / (1.0f + expf(-v1.y));
            }
            if (MODE == 2) {
                float2 r0v = *(const float2*)&Rp[r0 * N_ + cc];
                float2 r1v = *(const float2*)&Rp[(r0 + 8) * N_ + cc];
                v0.x += r0v.x; v0.y += r0v.y; v1.x += r1v.x; v1.y += r1v.y;
            }
            *(float2*)&C[r0 * N_ + cc] = v0;
            *(float2*)&C[(r0 + 8) * N_ + cc] = v1;
        }
}

// ---------------- LayerNorm (in place on g_x1), one warp per token ---------
__global__ void ln_kernel(const float* __restrict__ gamma,
                          const float* __restrict__ beta)
{
    int tok  = blockIdx.x * 8 + (threadIdx.x >> 5);
    int lane = threadIdx.x & 31;
    float4 v = *(float4*)&g_x1[tok * 128 + lane * 4];
    float s = v.x + v.y + v.z + v.w;
    float q = v.x * v.x + v.y * v.y + v.z * v.z + v.w * v.w;
    #pragma unroll
    for (int off = 16; off > 0; off >>= 1) {
        s += __shfl_xor_sync(0xFFFFFFFF, s, off);
        q += __shfl_xor_sync(0xFFFFFFFF, q, off);
    }
    float mu  = s * (1.0f / 128.0f);
    float var = q * (1.0f / 128.0f) - mu * mu;
    float rs  = rsqrtf(var + 1e-5f);
    float4 g = *(const float4*)&gamma[lane * 4];
    float4 b = *(const float4*)&beta [lane * 4];
    v.x = (v.x - mu) * rs * g.x + b.x;
    v.y = (v.y - mu) * rs * g.y + b.y;
    v.z = (v.z - mu) * rs * g.z + b.z;
    v.w = (v.w - mu) * rs * g.w + b.w;
    *(float4*)&g_x1[tok * 128 + lane * 4] = v;
}

// ---------------- Attention v2: smem-staged, coalesced ----------------------
// Block = (b, h, w-pair): 32 token-rows (2w x 16s) x 384 floats staged coalesced.
// Thread t: gl = t>>4 -> (nh = gl&7, wl = gl>>3), sq = t&15.
__global__ void __launch_bounds__(256) attn_kernel2()
{
    extern __shared__ float qs[];          // 32 rows x stride 388
    const int bid = blockIdx.x;
    const int wp = bid & 15;
    const int h  = (bid >> 4) & 31;
    const int b  = bid >> 9;
    const int w0 = wp * 2;
    const int t  = threadIdx.x;

    #pragma unroll
    for (int j = 0; j < 12; j++) {
        int idx = t + j * 256;             // 0..3071
        int ti = idx / 96, col4 = idx % 96;
        int s_ = ti >> 1, wl = ti & 1;
        float4 v = *(const float4*)&g_qkv[(((b * 16 + s_) * 1024) + h * 32 + w0 + wl) * 384 + col4 * 4];
        *(float4*)&qs[ti * 388 + col4 * 4] = v;
    }
    __syncthreads();

    const int gl = t >> 4, sq = t & 15;
    const int nh = gl & 7, wl = gl >> 3;
    const int ti_q = sq * 2 + wl;
    const float* qrow = &qs[ti_q * 388 + nh * 48];
    float q[16];
    #pragma unroll
    for (int d = 0; d < 16; d++) q[d] = qrow[d];

    float sc[16];
    float mx = -1e30f;
    #pragma unroll
    for (int l = 0; l < 16; l++) {
        const float* krow = &qs[(l * 2 + wl) * 388 + nh * 48 + 16];
        float d = 0.0f;
        #pragma unroll
        for (int dd = 0; dd < 16; dd++) d += q[dd] * krow[dd];
        float m = (l <= sq) ? 1.0f : -1000.0f;
        sc[l] = d * 0.25f + m;
        mx = fmaxf(mx, sc[l]);
    }
    float sum = 0.0f;
    #pragma unroll
    for (int l = 0; l < 16; l++) { sc[l] = expf(sc[l] - mx); sum += sc[l]; }
    float inv = 1.0f / sum;

    float o[16] = {};
    #pragma unroll
    for (int l = 0; l < 16; l++) {
        float pl = sc[l] * inv;
        const float* vrow = &qs[(l * 2 + wl) * 388 + nh * 48 + 32];
        #pragma unroll
        for (int dd = 0; dd < 16; dd++) o[dd] += pl * vrow[dd];
    }
    __syncthreads();                       // all k/v reads done before overwrite
    #pragma unroll
    for (int d = 0; d < 16; d++) qs[ti_q * 388 + nh * 16 + d] = o[d];
    __syncthreads();

    #pragma unroll
    for (int j = 0; j < 4; j++) {
        int idx = t + j * 256;             // 0..1023
        int ti = idx >> 5, col4 = idx & 31;
        int s_ = ti >> 1, wl2 = ti & 1;
        float4 v = *(float4*)&qs[ti * 388 + col4 * 4];
        *(float4*)&g_ao[(((b * 16 + s_) * 1024) + h * 32 + w0 + wl2) * 128 + col4 * 4] = v;
    }
}

// ---------------- init kernels ----------------------------------------------
__global__ void zero_hc_kernel()
{
    int idx = blockIdx.x * 256 + threadIdx.x;
    g_h[idx] = 0.0f;
    g_c[idx] = 0.0f;
}
__global__ void zero_pad_kernel()
{
    int idx = blockIdx.x * 256 + threadIdx.x;   // 8*256*34*36 = 2,506,752 exact
    g_pad[idx] = 0.0f;
}
__global__ void wprep_kernel(const float* __restrict__ convk)
{
    int idx = blockIdx.x * 256 + threadIdx.x;   // 9*256*512
    if (idx >= 9 * 256 * 512) return;
    int oc = idx & 511;
    int ic = (idx >> 9) & 255;
    int tp = idx >> 17;
    g_wp[idx] = tf32r(convk[(oc * 256 + ic) * 9 + tp]);
}

// ---------------- pack per-step conv input (row stride 36) ------------------
__global__ void pack_kernel(int s)
{
    __shared__ float tile[32][33];
    const int b   = blockIdx.z;
    const int icg = blockIdx.y;
    const int y   = blockIdx.x;
    const int t   = threadIdx.x;
    const int e   = icg * 32 + (t & 31);

    #pragma unroll
    for (int it = 0; it < 4; it++) {
        int x   = (t >> 5) + it * 8;
        int pix = y * 32 + x;
        float v = (e < 128)
            ? g_xr[((b * 16 + s) * 1024 + pix) * 128 + e]
            : g_h [(b * 1024 + pix) * 128 + (e - 128)];
        tile[x][t & 31] = v;
    }
    __syncthreads();
    #pragma unroll
    for (int it = 0; it < 4; it++) {
        int icl = (t >> 5) + it * 8;
        int ic  = icg * 32 + icl;
        int x   = t & 31;
        g_pad[((b * 256 + ic) * 34 + (y + 1)) * 36 + (x + 1)] = tf32r(tile[x][icl]);
    }
}

// ---------------- tensor-core conv with cp.async double buffering -----------
// Block: 128 px (4 rows x 32) x 64 oc, 8 warps. 32 ic-chunks of 8, ping-pong.
__global__ void __launch_bounds__(256) conv_mma_kernel(int s)
{
    extern __shared__ uint32_t sh[];
    uint32_t* in_base = sh;                 // 2 x 1728  ([ic8][row6][col36])
    uint32_t* w_base  = sh + 2 * 1728;      // 2 x 5184  ([tap9][ic8][oc 64 pad 72])

    const int b    = blockIdx.z;
    const int y0   = blockIdx.y * 4;
    const int ocB  = blockIdx.x * 64;
    const int t    = threadIdx.x;
    const int lane = t & 31;
    const int warp = t >> 5;
    const int wm   = warp & 3;
    const int wn   = warp >> 2;
    const int icl  = lane & 3;
    const int ocl  = wn * 32 + (lane >> 2);

    // precompute cp.async assignments
    int in_dst[2], in_rel[2]; bool in_ok[2];
    #pragma unroll
    for (int j = 0; j < 2; j++) {
        int idx = t + j * 256;
        in_ok[j] = idx < 432;
        int i = idx / 54, rem = idx % 54;
        int row = rem / 9, col4 = rem % 9;
        in_dst[j] = i * 216 + row * 36 + col4 * 4;
        in_rel[j] = i * 1224 + (y0 + row) * 36 + col4 * 4;    // 1224 = 34*36
    }
    int w_dst[5], w_rel[5]; bool w_ok[5];
    #pragma unroll
    for (int j = 0; j < 5; j++) {
        int idx = t + j * 256;
        w_ok[j] = idx < 1152;
        int o4 = idx & 15, i = (idx >> 4) & 7, tp = idx >> 7;
        w_dst[j] = (tp * 8 + i) * 72 + o4 * 4;
        w_rel[j] = tp * 131072 + i * 512 + ocB + o4 * 4;       // 131072 = 256*512
    }
    const float* in_src = g_pad + b * 256 * 1224;
    const uint32_t sm_in = sm_u32(in_base);
    const uint32_t sm_w  = sm_u32(w_base);

    auto load_chunk = [&](int stage, int ic0) {
        uint32_t ib = sm_in + (uint32_t)stage * 1728u * 4u;
        uint32_t wb = sm_w  + (uint32_t)stage * 5184u * 4u;
        #pragma unroll
        for (int j = 0; j < 2; j++)
            if (in_ok[j]) cpa16(ib + in_dst[j] * 4, in_src + ic0 * 1224 + in_rel[j]);
        #pragma unroll
        for (int j = 0; j < 5; j++)
            if (w_ok[j]) cpa16(wb + w_dst[j] * 4, g_wp + ic0 * 512 + w_rel[j]);
        asm volatile("cp.async.commit_group;\n");
    };

    float acc[2][4][4] = {};
    load_chunk(0, 0);

    for (int c = 0; c < 32; c++) {
        const int stage = c & 1;
        if (c < 31) {
            load_chunk(stage ^ 1, (c + 1) * 8);
            asm volatile("cp.async.wait_group 1;\n");
        } else {
            asm volatile("cp.async.wait_group 0;\n");
        }
        __syncthreads();

        const uint32_t* in_s = in_base + stage * 1728;
        const uint32_t* w_s  = w_base  + stage * 5184;

        #pragma unroll
        for (int tp = 0; tp < 9; tp++) {
            const int ky = tp / 3, kx = tp % 3;
            uint32_t bf[4][2];
            #pragma unroll
            for (int g = 0; g < 4; g++) {
                bf[g][0] = w_s[(tp * 8 + icl    ) * 72 + ocl + g * 8];
                bf[g][1] = w_s[(tp * 8 + icl + 4) * 72 + ocl + g * 8];
            }
            const int rr = wm + ky;
            #pragma unroll
            for (int f = 0; f < 2; f++) {
                int xx = f * 16 + (lane >> 2) + kx;
                uint32_t a0 = in_s[(icl * 6 + rr) * 36 + xx];
                uint32_t a1 = in_s[(icl * 6 + rr) * 36 + xx + 8];
                uint32_t a2 = in_s[((icl + 4) * 6 + rr) * 36 + xx];
                uint32_t a3 = in_s[((icl + 4) * 6 + rr) * 36 + xx + 8];
                #pragma unroll
                for (int g = 0; g < 4; g++) {
                    asm volatile(
                        "mma.sync.aligned.m16n8k8.row.col.f32.tf32.tf32.f32 "
                        "{%0,%1,%2,%3}, {%4,%5,%6,%7}, {%8,%9}, {%0,%1,%2,%3};"
                        : "+f"(acc[f][g][0]), "+f"(acc[f][g][1]),
                          "+f"(acc[f][g][2]), "+f"(acc[f][g][3])
                        : "r"(a0), "r"(a1), "r"(a2), "r"(a3),
                          "r"(bf[g][0]), "r"(bf[g][1]));
                }
            }
        }
        __syncthreads();
    }

    #pragma unroll
    for (int f = 0; f < 2; f++) {
        #pragma unroll
        for (int g = 0; g < 4; g++) {
            int n  = ocB + wn * 32 + g * 8 + 2 * (lane & 3);
            int x0 = f * 16 + (lane >> 2);
            int pix0 = (y0 + wm) * 32 + x0;
            int pix1 = pix0 + 8;
            float2 v0 = {acc[f][g][0], acc[f][g][1]};
            float2 v1 = {acc[f][g][2], acc[f][g][3]};
            *(float2*)&g_cc[(b * 1024 + pix0) * 512 + n] = v0;
            *(float2*)&g_cc[(b * 1024 + pix1) * 512 + n] = v1;
        }
    }
}

// ---------------- LSTM gates + state update + output write -----------------
__global__ void gates_kernel(int s, float* __restrict__ out)
{
    int idx = blockIdx.x * 256 + threadIdx.x;
    int e      = idx & 127;
    int pix_b  = idx >> 7;
    const float* cc = g_cc + pix_b * 512;
    float ci = cc[e];
    float cf = cc[128 + e];
    float co = cc[256 + e];
    float cg = cc[384 + e];
    float c  = g_c[idx];
    float si = 1.0f / (1.0f + expf(-ci));
    float sf = 1.0f / (1.0f + expf(-cf));
    float so = 1.0f / (1.0f + expf(-co));
    float cn = sf * c + si * tanhf(cg);
    float hn = so * tanhf(cn);
    g_c[idx] = cn;
    g_h[idx] = hn;
    int b   = pix_b >> 10;
    int pix = pix_b & 1023;
    out[((b * 16 + s) * 1024 + pix) * 128 + e] = hn;
}

// ---------------- launch ----------------------------------------------------
extern "C" void kernel_launch(void* const* d_in, const int* in_sizes, int n_in,
                              void* d_out, int out_size)
{
    const float* inputs = (const float*)d_in[0];
    const float* W_proj = (const float*)d_in[1];
    const float* gamma  = (const float*)d_in[2];
    const float* beta   = (const float*)d_in[3];
    const float* W_in   = (const float*)d_in[4];
    const float* W_out  = (const float*)d_in[5];
    const float* convk  = (const float*)d_in[6];
    float* out = (float*)d_out;

    const int GEMM_SMEM = (16896 + 17408) * 4;      // 137216
    const int ATTN_SMEM = 32 * 388 * 4;             // 49664
    const int CONV_SMEM = (2 * 1728 + 2 * 5184) * 4; // 55296
    cudaFuncSetAttribute(gemm_mma_kernel<128, 0>, cudaFuncAttributeMaxDynamicSharedMemorySize, GEMM_SMEM);
    cudaFuncSetAttribute(gemm_mma_kernel<384, 1>, cudaFuncAttributeMaxDynamicSharedMemorySize, GEMM_SMEM);
    cudaFuncSetAttribute(gemm_mma_kernel<128, 2>, cudaFuncAttributeMaxDynamicSharedMemorySize, GEMM_SMEM);
    cudaFuncSetAttribute(attn_kernel2, cudaFuncAttributeMaxDynamicSharedMemorySize, ATTN_SMEM);
    cudaFuncSetAttribute(conv_mma_kernel, cudaFuncAttributeMaxDynamicSharedMemorySize, CONV_SMEM);

    // 1) x = silu(inputs @ W_proj)
    gemm_mma_kernel<128, 0><<<dim3(NTOK / 128, 1), 256, GEMM_SMEM>>>(inputs, W_proj, nullptr);
    // 2) LayerNorm (in place)
    ln_kernel<<<NTOK / 8, 256>>>(gamma, beta);
    // 3) qkv = x @ W_in
    gemm_mma_kernel<384, 1><<<dim3(NTOK / 128, 3), 256, GEMM_SMEM>>>(nullptr, W_in, nullptr);
    // 4) attention
    attn_kernel2<<<BB * HH * (WW / 2), 256, ATTN_SMEM>>>();
    // 5) x = ao @ W_out + inputs
    gemm_mma_kernel<128, 2><<<dim3(NTOK / 128, 1), 256, GEMM_SMEM>>>(nullptr, W_out, inputs);
    // 6) init
    zero_hc_kernel<<<(NPIX * EE) / 256, 256>>>();
    zero_pad_kernel<<<(BB * 256 * 34 * 36) / 256, 256>>>();
    wprep_kernel<<<(9 * 256 * 512 + 255) / 256, 256>>>(convk);
    // 7) ConvLSTM scan
    for (int s = 0; s < SS; s++) {
        pack_kernel<<<dim3(32, 8, 8), 256>>>(s);
        conv_mma_kernel<<<dim3(8, 8, 8), 256, CONV_SMEM>>>(s);
        gates_kernel<<<(NPIX * EE) / 256, 256>>>(s, out);
    }
}